// round 12
// baseline (speedup 1.0000x reference)
#include <cuda_runtime.h>
#include <math.h>

#define BATCH 16
#define LSEQ  720
#define ECH   64
#define OUTL  96
#define NDIM  6144            // (2k+c)*96+u = 64*96
#define CH_D  24

typedef unsigned long long ull;

__device__ __forceinline__ ull dup2(float x){
    ull r;
    asm("mov.b64 %0, {%1, %1};" : "=l"(r) : "f"(x));
    return r;
}
__device__ __forceinline__ void fma2(ull &d, ull a, ull b){
    asm("fma.rn.f32x2 %0, %1, %2, %0;" : "+l"(d) : "l"(a), "l"(b));
}

// ---------------- static device scratch ----------------
__device__ float g_mean[BATCH*ECH];
__device__ float g_std [BATCH*ECH];
__device__ float g_K[3][384][256];            // Krylov kernels K_d = Ad^d Bd (atomic dst)
__device__ float g_Pw[10][3][65536];          // P^(2^r) per round (atomic dst for r>=1)
__device__ float g_E[3][256*96];              // mlp_w[s]*ev[s]^T  (o,u)
__device__ float g_WE[3][256*NDIM];           // Wc@E, mag folded
__device__ float g_C[672*NDIM];               // K@WE
__device__ float g_Mpart[96][384*96];         // per (s,k) chain partials
__device__ float g_M[384*96];

__constant__ int c_tile_s[11] = {0,0,1,1,1,2,2,2,2,2,2};
__constant__ int c_tile_r[11] = {0,64,0,64,128,0,64,128,192,256,320};

__device__ __forceinline__ int seg_off(int s){ return s==0?0:(s==1?96:288); }
__device__ __forceinline__ int seg_T  (int s){ return s==0?96:(s==1?192:384); }

// ---------------- 1. per-(b,e) mean / std ----------------
__global__ void stats_kernel(const float* __restrict__ x){
    int b = blockIdx.x;
    int t = threadIdx.x;
    int e = t & 63, q = t >> 6;
    float s = 0.f, sq = 0.f;
    for (int l = q; l < LSEQ; l += 4){
        float v = x[((size_t)b*LSEQ + l)*ECH + e];
        s += v; sq += v*v;
    }
    __shared__ float sh[2][4][64];
    sh[0][q][e] = s; sh[1][q][e] = sq;
    __syncthreads();
    if (q == 0){
        float S  = sh[0][0][e]+sh[0][1][e]+sh[0][2][e]+sh[0][3][e];
        float SQ = sh[1][0][e]+sh[1][1][e]+sh[1][2][e]+sh[1][3][e];
        float m = S * (1.f/LSEQ);
        float var = SQ * (1.f/LSEQ) - m*m;
        g_mean[b*ECH+e] = m;
        g_std [b*ECH+e] = sqrtf(var + 1e-5f);
    }
}

// ---------------- 2. E[s][o][u] = mlp_w[s] * ev[s,u,o] ----------------
__global__ void egen_kernel(const float* __restrict__ ev, const float* __restrict__ mlp_w){
    int s = blockIdx.x;
    int o = threadIdx.x;
    float w = mlp_w[s];
    for (int u = 0; u < 96; u++)
        g_E[s][o*96 + u] = w * ev[((size_t)(s*96+u))*256 + o];
}

// ---------------- 3. init: Pw[0]=Ad; zero Pw[1..9]; K row0=Bd, rest 0 -------
#define N1 196608          // 3*65536
#define N2 1769472         // 9*3*65536
#define N3 294912          // 3*384*256
__global__ void init_kernel(const float* __restrict__ A, const float* __restrict__ Bv){
    int idx = blockIdx.x*blockDim.x + threadIdx.x;
    float* pw = &g_Pw[0][0][0];
    if (idx < N1){
        pw[idx] = A[idx];
    } else if (idx < N1 + N2){
        pw[idx] = 0.f;
    } else if (idx < N1 + N2 + N3){
        int j = idx - (N1 + N2);
        int s = j / 98304, rem = j % 98304;
        int d = rem >> 8, i = rem & 255;
        g_K[s][d][i] = d ? 0.f : Bv[s*256 + i];
    }
}

// ---------------- 4. log-doubling round (split-K=2, atomic reduce) ----------
// task 0: K[n..n+m) += K[0..m) @ (P^n)^T   (m=min(n,T-n))
// task 1: P^{2n}    += P^n @ P^n           (only if 2n < T)
__global__ void rgemm_kernel(int r){
    int s = blockIdx.y;
    int task  = blockIdx.z >> 1;
    int split = blockIdx.z & 1;
    int Ts = seg_T(s);
    int n = 1 << r;
    int rows; const float *Aop, *Bop; float* Cop; bool nt;
    if (task == 0){
        if (n >= Ts) return;
        rows = min(n, Ts - n);
        Aop = &g_K[s][0][0];
        Bop = g_Pw[r][s];
        Cop = &g_K[s][n][0];
        nt  = true;
    } else {
        if (2*n >= Ts) return;
        rows = 256;
        Aop = g_Pw[r][s];
        Bop = Aop;
        Cop = g_Pw[r+1][s];
        nt  = false;
    }
    int tile = blockIdx.x;
    int rowt = tile >> 2, colt = tile & 3;
    if (rowt*64 >= rows) return;
    int row0 = rowt*64, col0 = colt*64;
    __shared__ float As[16][68];
    __shared__ float Bs[16][68];
    int t = threadIdx.x;
    int tm4 = (t >> 4) * 4;
    int tn4 = (t & 15) * 4;
    ull acc2[8];
    #pragma unroll
    for (int q = 0; q < 8; q++) acc2[q] = 0ull;
    int k0 = split*128;
    #pragma unroll
    for (int ch = 0; ch < 8; ch++){
        int kc = k0 + ch*16;
        #pragma unroll
        for (int p = 0; p < 4; p++){
            int idx = t + p*256;
            int kk = idx & 15, m = idx >> 4;
            As[kk][m] = (row0 + m < rows) ? Aop[(size_t)(row0+m)*256 + kc + kk] : 0.f;
        }
        #pragma unroll
        for (int p = 0; p < 4; p++){
            int idx = t + p*256;
            int kk = idx & 15, j = idx >> 4;
            Bs[kk][j] = nt ? Bop[(size_t)(col0+j)*256 + kc + kk]
                           : Bop[(size_t)(kc+kk)*256 + col0 + j];
        }
        __syncthreads();
        #pragma unroll
        for (int kk = 0; kk < 16; kk++){
            float4 av = *(const float4*)&As[kk][tm4];
            ull bv0 = *(const ull*)&Bs[kk][tn4];
            ull bv1 = *(const ull*)&Bs[kk][tn4+2];
            ull a0 = dup2(av.x), a1 = dup2(av.y), a2 = dup2(av.z), a3 = dup2(av.w);
            fma2(acc2[0], a0, bv0); fma2(acc2[1], a0, bv1);
            fma2(acc2[2], a1, bv0); fma2(acc2[3], a1, bv1);
            fma2(acc2[4], a2, bv0); fma2(acc2[5], a2, bv1);
            fma2(acc2[6], a3, bv0); fma2(acc2[7], a3, bv1);
        }
        __syncthreads();
    }
    #pragma unroll
    for (int a = 0; a < 4; a++){
        int m = row0 + tm4 + a;
        if (m < rows){
            float2 v0 = *(float2*)&acc2[a*2];
            float2 v1 = *(float2*)&acc2[a*2+1];
            float* dst = &Cop[(size_t)m*256 + col0 + tn4];
            atomicAdd(dst+0, v0.x);
            atomicAdd(dst+1, v0.y);
            atomicAdd(dst+2, v1.x);
            atomicAdd(dst+3, v1.y);
        }
    }
}

// ---------------- 5. WE[s][i][(2k+c)*96+u] = mag_k * sum_o w[i,o,k]*E[o,u] ---
// float4 global loads; Bs rows padded to 100 for aligned STS.128.
__global__ void wegemm_kernel(const float* __restrict__ wr, const float* __restrict__ wi){
    int i = blockIdx.x, s = blockIdx.y;
    int T = seg_T(s);
    __shared__ __align__(16) float As[2][16][68];   // [o'][2k+c]
    __shared__ __align__(16) float Bs[2][16][100];  // [o'][u]
    const float* wrp = wr + ((size_t)(s*256 + i)*256)*32;
    const float* wip = wi + ((size_t)(s*256 + i)*256)*32;
    const float* E = g_E[s];
    int t = threadIdx.x;
    int a = t >> 4, b = t & 15;
    // load-role indices
    int sel = t >> 7;               // 0: wr, 1: wi
    int q = t & 127;
    int lo = q >> 3;                // o row 0..15
    int k4 = (q & 7) * 4;           // k group
    const float* wsel = sel ? wip : wrp;
    int eo0 = t / 24,  ec0 = (t % 24) * 4;           // E float4 slot 0
    int e1 = t + 256;
    int eo1 = e1 / 24, ec1 = (e1 % 24) * 4;          // E float4 slot 1 (t<128)
    ull acc2[12];
    #pragma unroll
    for (int p = 0; p < 12; p++) acc2[p] = 0ull;

    // chunk 0
    {
        float4 v = *(const float4*)&wsel[lo*32 + k4];
        As[0][lo][2*k4 + sel]     = v.x;
        As[0][lo][2*(k4+1) + sel] = v.y;
        As[0][lo][2*(k4+2) + sel] = v.z;
        As[0][lo][2*(k4+3) + sel] = v.w;
        *(float4*)&Bs[0][eo0][ec0] = *(const float4*)&E[eo0*96 + ec0];
        if (t < 128)
            *(float4*)&Bs[0][eo1][ec1] = *(const float4*)&E[eo1*96 + ec1];
    }
    __syncthreads();

    float4 rw, re0, re1;
    for (int c = 0; c < 16; c++){
        int cur = c & 1;
        if (c < 15){
            int oc = (c+1)*16;
            rw = *(const float4*)&wsel[(oc+lo)*32 + k4];
            re0 = *(const float4*)&E[(oc+eo0)*96 + ec0];
            if (t < 128) re1 = *(const float4*)&E[(oc+eo1)*96 + ec1];
        }
        #pragma unroll
        for (int o = 0; o < 16; o++){
            float4 av = *(const float4*)&As[cur][o][a*4];
            ull b0 = *(const ull*)&Bs[cur][o][b*6];
            ull b1 = *(const ull*)&Bs[cur][o][b*6+2];
            ull b2 = *(const ull*)&Bs[cur][o][b*6+4];
            ull a0 = dup2(av.x), a1 = dup2(av.y), a2 = dup2(av.z), a3 = dup2(av.w);
            fma2(acc2[0],  a0, b0); fma2(acc2[1],  a0, b1); fma2(acc2[2],  a0, b2);
            fma2(acc2[3],  a1, b0); fma2(acc2[4],  a1, b1); fma2(acc2[5],  a1, b2);
            fma2(acc2[6],  a2, b0); fma2(acc2[7],  a2, b1); fma2(acc2[8],  a2, b2);
            fma2(acc2[9],  a3, b0); fma2(acc2[10], a3, b1); fma2(acc2[11], a3, b2);
        }
        if (c < 15){
            int nxt = cur ^ 1;
            As[nxt][lo][2*k4 + sel]     = rw.x;
            As[nxt][lo][2*(k4+1) + sel] = rw.y;
            As[nxt][lo][2*(k4+2) + sel] = rw.z;
            As[nxt][lo][2*(k4+3) + sel] = rw.w;
            *(float4*)&Bs[nxt][eo0][ec0] = re0;
            if (t < 128)
                *(float4*)&Bs[nxt][eo1][ec1] = re1;
        }
        __syncthreads();
    }
    float invT = 1.f/(float)T;
    float* out = g_WE[s] + (size_t)i*NDIM;
    #pragma unroll
    for (int p = 0; p < 4; p++){
        int kc = a*4 + p;
        int k = kc >> 1;
        float mag = (k == 0) ? invT : 2.f*invT;
        #pragma unroll
        for (int j = 0; j < 3; j++){
            float2 v = *(float2*)&acc2[p*3+j];
            out[kc*96 + b*6 + 2*j]     = v.x*mag;
            out[kc*96 + b*6 + 2*j + 1] = v.y*mag;
        }
    }
}

// ---------------- 6. C = K @ WE  (per-scale, double-buffered) ----------------
__global__ void cgemm_kernel(){
    int colt = blockIdx.x;          // 0..95
    int rowt = blockIdx.y;          // 0..10
    int s = c_tile_s[rowt], row0 = c_tile_r[rowt];
    int Ts = seg_T(s), seg = seg_off(s);
    int col0 = colt*64;
    const float* A = &g_K[s][0][0];
    const float* B = g_WE[s];
    __shared__ float As[2][16][68];
    __shared__ float Bs[2][16][68];
    int t = threadIdx.x;
    int tm4 = (t >> 4) * 4;
    int tn4 = (t & 15) * 4;
    ull acc2[8];
    #pragma unroll
    for (int q = 0; q < 8; q++) acc2[q] = 0ull;

    #pragma unroll
    for (int p = 0; p < 4; p++){
        int idx = t + p*256;
        int kk = idx & 15, m = idx >> 4;
        As[0][kk][m] = (row0 + m < Ts) ? A[(size_t)(row0+m)*256 + kk] : 0.f;
    }
    #pragma unroll
    for (int p = 0; p < 4; p++){
        int idx = t + p*256;
        int j = idx & 63, kk = idx >> 6;
        Bs[0][kk][j] = B[(size_t)kk*NDIM + col0 + j];
    }
    __syncthreads();

    float ra[4], rb[4];
    for (int c = 0; c < 16; c++){
        int cur = c & 1;
        if (c < 15){
            int kc = (c+1)*16;
            #pragma unroll
            for (int p = 0; p < 4; p++){
                int idx = t + p*256;
                int kk = idx & 15, m = idx >> 4;
                ra[p] = (row0 + m < Ts) ? A[(size_t)(row0+m)*256 + kc + kk] : 0.f;
            }
            #pragma unroll
            for (int p = 0; p < 4; p++){
                int idx = t + p*256;
                int j = idx & 63, kk = idx >> 6;
                rb[p] = B[(size_t)(kc+kk)*NDIM + col0 + j];
            }
        }
        #pragma unroll
        for (int kk = 0; kk < 16; kk++){
            float4 av = *(const float4*)&As[cur][kk][tm4];
            ull bv0 = *(const ull*)&Bs[cur][kk][tn4];
            ull bv1 = *(const ull*)&Bs[cur][kk][tn4+2];
            ull a0 = dup2(av.x), a1 = dup2(av.y), a2 = dup2(av.z), a3 = dup2(av.w);
            fma2(acc2[0], a0, bv0); fma2(acc2[1], a0, bv1);
            fma2(acc2[2], a1, bv0); fma2(acc2[3], a1, bv1);
            fma2(acc2[4], a2, bv0); fma2(acc2[5], a2, bv1);
            fma2(acc2[6], a3, bv0); fma2(acc2[7], a3, bv1);
        }
        if (c < 15){
            int nxt = cur ^ 1;
            #pragma unroll
            for (int p = 0; p < 4; p++){
                int idx = t + p*256;
                As[nxt][idx & 15][idx >> 4] = ra[p];
            }
            #pragma unroll
            for (int p = 0; p < 4; p++){
                int idx = t + p*256;
                Bs[nxt][idx >> 6][idx & 63] = rb[p];
            }
        }
        __syncthreads();
    }
    #pragma unroll
    for (int a = 0; a < 4; a++){
        int row = row0 + tm4 + a;
        if (row < Ts){
            float* outp = &g_C[(size_t)(seg+row)*NDIM + col0 + tn4];
            *(float2*)outp       = *(float2*)&acc2[a*2];
            *(float2*)(outp + 2) = *(float2*)&acc2[a*2+1];
        }
    }
}

// ---------------- 7. prefix-sum chain, smem-staged ----------------
__global__ void chain_kernel(){
    int k = blockIdx.x;             // 0..31
    int s = blockIdx.y;             // 0..2
    int T = seg_T(s), seg = seg_off(s);
    int u = threadIdx.x;            // 0..95
    __shared__ float buf[2][CH_D][192];
    __shared__ float2 tw[384];
    for (int m = u; m < T; m += 96){
        float sv, cv;
        sincosf(6.28318530717958647692f*(float)m/(float)T, &sv, &cv);
        tw[m] = make_float2(cv, sv);
    }
    const float* Cb = g_C + (size_t)seg*NDIM + (2*k)*96;
    #pragma unroll
    for (int q = 0; q < 12; q++){
        int j = u + q*96;
        int row = j/48, col = j%48;
        ((float4*)buf[0][row])[col] = ((const float4*)(Cb + (size_t)row*NDIM))[col];
    }
    __syncthreads();
    int nch = T / CH_D;
    int m0 = ((96 - T) % T + T) % T;
    int p1 = 0;
    int p2 = (int)(((long long)k * (long long)m0) % (long long)T);
    float Pr = 0.f, Pi = 0.f;
    float* Mp = g_Mpart[s*32+k] + u;
    for (int c = 0; c < nch; c++){
        int cur = c & 1;
        if (c + 1 < nch){
            const float* src = Cb + (size_t)(c+1)*CH_D*NDIM;
            #pragma unroll
            for (int q = 0; q < 12; q++){
                int j = u + q*96;
                int row = j/48, col = j%48;
                ((float4*)buf[cur^1][row])[col] = ((const float4*)(src + (size_t)row*NDIM))[col];
            }
        }
        #pragma unroll 4
        for (int dd = 0; dd < CH_D; dd++){
            int d = c*CH_D + dd;
            float Cr = buf[cur][dd][u];
            float Ci = buf[cur][dd][u+96];
            float2 t1 = tw[p1];
            Pr += Cr*t1.x + Ci*t1.y;
            Pi += Ci*t1.x - Cr*t1.y;
            float2 t2 = tw[p2];
            Mp[(size_t)(383-d)*96] = t2.x*Pr - t2.y*Pi;
            p1 += k; if (p1 >= T) p1 -= T;
            p2 += k; if (p2 >= T) p2 -= T;
        }
        __syncthreads();
    }
}

// ---------------- 8. reduce Mpart over (s,k) with validity ranges ----------
__global__ void mreduce_kernel(){
    int idx = blockIdx.x*256 + threadIdx.x;   // 0..36863
    if (idx >= 384*96) return;
    int g = idx / 96;
    float a = 0.f;
    #pragma unroll 8
    for (int p = 64; p < 96; p++) a += g_Mpart[p][idx];   // s2: all g
    if (g >= 192){
        #pragma unroll 8
        for (int p = 32; p < 64; p++) a += g_Mpart[p][idx];
    }
    if (g >= 288){
        #pragma unroll 8
        for (int p = 0; p < 32; p++) a += g_Mpart[p][idx];
    }
    g_M[idx] = a;
}

// ---------------- 9. final (msum folded in) ----------------
__global__ void final_kernel(const float* __restrict__ x,
                             const float* __restrict__ mlp_b,
                             float* __restrict__ out){
    int b = blockIdx.x, u = blockIdx.y;
    int e = threadIdx.x;   // 64
    __shared__ float msh[384];
    for (int g = e; g < 384; g += 64) msh[g] = g_M[g*96 + u];
    __syncthreads();
    const float* xp = x + ((size_t)b*LSEQ + 336)*ECH + e;
    float acc = 0.f, msum = 0.f;
    #pragma unroll 8
    for (int g = 0; g < 384; g++){
        float mv = msh[g];
        acc += xp[(size_t)g*ECH] * mv;
        msum += mv;
    }
    float mean = g_mean[b*ECH+e], sd = g_std[b*ECH+e];
    out[((size_t)b*OUTL + u)*ECH + e] = acc + mean*(1.f - msum) + mlp_b[0]*sd;
}

// ---------------- launch (multi-stream fork/join, graph-capturable) --------
extern "C" void kernel_launch(void* const* d_in, const int* in_sizes, int n_in,
                              void* d_out, int out_size){
    const float* x     = (const float*)d_in[0];
    const float* wr    = (const float*)d_in[1];
    const float* wi    = (const float*)d_in[2];
    const float* mlp_w = (const float*)d_in[3];
    const float* mlp_b = (const float*)d_in[4];
    const float* A     = (const float*)d_in[5];
    const float* Bv    = (const float*)d_in[6];
    const float* ev    = (const float*)d_in[7];
    float* out = (float*)d_out;

    static cudaStream_t sB = 0, sC = 0;
    static cudaEvent_t eFork = 0, eB = 0, eC = 0;
    if (!sB){
        cudaStreamCreateWithFlags(&sB, cudaStreamNonBlocking);
        cudaStreamCreateWithFlags(&sC, cudaStreamNonBlocking);
        cudaEventCreateWithFlags(&eFork, cudaEventDisableTiming);
        cudaEventCreateWithFlags(&eB, cudaEventDisableTiming);
        cudaEventCreateWithFlags(&eC, cudaEventDisableTiming);
    }

    // fork
    cudaEventRecord(eFork, 0);
    cudaStreamWaitEvent(sB, eFork, 0);
    cudaStreamWaitEvent(sC, eFork, 0);

    // stream C: stats (only needed by final)
    stats_kernel<<<BATCH, 256, 0, sC>>>(x);
    cudaEventRecord(eC, sC);

    // stream B: weight-side pipeline
    egen_kernel<<<3, 256, 0, sB>>>(ev, mlp_w);
    wegemm_kernel<<<dim3(256,3), 256, 0, sB>>>(wr, wi);
    cudaEventRecord(eB, sB);

    // stream 0: Krylov rounds (split-K=2)
    init_kernel<<<(N1+N2+N3+255)/256, 256>>>(A, Bv);
    for (int r = 0; r < 9; r++)
        rgemm_kernel<<<dim3(16,3,4), 256>>>(r);

    // join B, then the C-path
    cudaStreamWaitEvent(0, eB, 0);
    cgemm_kernel<<<dim3(96,11), 256>>>();
    chain_kernel<<<dim3(32,3), 96>>>();
    mreduce_kernel<<<144, 256>>>();

    // join C, final
    cudaStreamWaitEvent(0, eC, 0);
    final_kernel<<<dim3(BATCH, OUTL), 64>>>(x, mlp_b, out);
}

// round 13
// speedup vs baseline: 1.1266x; 1.1266x over previous
#include <cuda_runtime.h>
#include <math.h>

#define BATCH 16
#define LSEQ  720
#define ECH   64
#define OUTL  96
#define NDIM  6144            // (2k+c)*96+u = 64*96
#define CH_D  24

typedef unsigned long long ull;

__device__ __forceinline__ ull dup2(float x){
    ull r;
    asm("mov.b64 %0, {%1, %1};" : "=l"(r) : "f"(x));
    return r;
}
__device__ __forceinline__ void fma2(ull &d, ull a, ull b){
    asm("fma.rn.f32x2 %0, %1, %2, %0;" : "+l"(d) : "l"(a), "l"(b));
}

// ---------------- static device scratch ----------------
__device__ float g_mean[BATCH*ECH];
__device__ float g_std [BATCH*ECH];
__device__ float g_K[3][384][256];            // Krylov kernels K_d = Ad^d Bd (atomic dst)
__device__ float g_Pw[10][3][65536];          // P^(2^r) per round (atomic dst for r>=1)
__device__ float g_E[3][256*96];              // mlp_w[s]*ev[s]^T  (o,u)
__device__ float g_WE[3][256*NDIM];           // Wc@E, mag folded
__device__ float g_C[672*NDIM];               // K@WE
__device__ float g_Mpart[96][384*96];         // per (s,k) chain partials
__device__ float g_M[384*96];

__constant__ int c_tile_s[11] = {0,0,1,1,1,2,2,2,2,2,2};
__constant__ int c_tile_r[11] = {0,64,0,64,128,0,64,128,192,256,320};

__device__ __forceinline__ int seg_off(int s){ return s==0?0:(s==1?96:288); }
__device__ __forceinline__ int seg_T  (int s){ return s==0?96:(s==1?192:384); }

// ---------------- 1. merged prep: blocks 0..15 stats, 16..18 egen ----------
__global__ void prep_kernel(const float* __restrict__ x,
                            const float* __restrict__ ev,
                            const float* __restrict__ mlp_w){
    int bid = blockIdx.x;
    int t = threadIdx.x;
    if (bid < BATCH){
        int b = bid;
        int e = t & 63, q = t >> 6;
        float s = 0.f, sq = 0.f;
        for (int l = q; l < LSEQ; l += 4){
            float v = x[((size_t)b*LSEQ + l)*ECH + e];
            s += v; sq += v*v;
        }
        __shared__ float sh[2][4][64];
        sh[0][q][e] = s; sh[1][q][e] = sq;
        __syncthreads();
        if (q == 0){
            float S  = sh[0][0][e]+sh[0][1][e]+sh[0][2][e]+sh[0][3][e];
            float SQ = sh[1][0][e]+sh[1][1][e]+sh[1][2][e]+sh[1][3][e];
            float m = S * (1.f/LSEQ);
            float var = SQ * (1.f/LSEQ) - m*m;
            g_mean[b*ECH+e] = m;
            g_std [b*ECH+e] = sqrtf(var + 1e-5f);
        }
    } else {
        int s = bid - BATCH;
        int o = t;
        float w = mlp_w[s];
        for (int u = 0; u < 96; u++)
            g_E[s][o*96 + u] = w * ev[((size_t)(s*96+u))*256 + o];
    }
}

// ---------------- 3. init: Pw[0]=Ad; zero Pw[1..9]; K row0=Bd, rest 0 -------
#define N1 196608          // 3*65536
#define N2 1769472         // 9*3*65536
#define N3 294912          // 3*384*256
__global__ void init_kernel(const float* __restrict__ A, const float* __restrict__ Bv){
    int idx = blockIdx.x*blockDim.x + threadIdx.x;
    float* pw = &g_Pw[0][0][0];
    if (idx < N1){
        pw[idx] = A[idx];
    } else if (idx < N1 + N2){
        pw[idx] = 0.f;
    } else if (idx < N1 + N2 + N3){
        int j = idx - (N1 + N2);
        int s = j / 98304, rem = j % 98304;
        int d = rem >> 8, i = rem & 255;
        g_K[s][d][i] = d ? 0.f : Bv[s*256 + i];
    }
}

// ---------------- 4. log-doubling round (split-K=16, single pass) ----------
// task 0: K[n..n+m) += K[0..m) @ (P^n)^T   (m=min(n,T-n))
// task 1: P^{2n}    += P^n @ P^n           (only if 2n < T)
__global__ void rgemm_kernel(int r){
    int s = blockIdx.y;
    int task  = blockIdx.z >> 4;
    int split = blockIdx.z & 15;
    int Ts = seg_T(s);
    int n = 1 << r;
    int rows; const float *Aop, *Bop; float* Cop; bool nt;
    if (task == 0){
        if (n >= Ts) return;
        rows = min(n, Ts - n);
        Aop = &g_K[s][0][0];
        Bop = g_Pw[r][s];
        Cop = &g_K[s][n][0];
        nt  = true;
    } else {
        if (2*n >= Ts) return;
        rows = 256;
        Aop = g_Pw[r][s];
        Bop = Aop;
        Cop = g_Pw[r+1][s];
        nt  = false;
    }
    int tile = blockIdx.x;
    int rowt = tile >> 2, colt = tile & 3;
    if (rowt*64 >= rows) return;
    int row0 = rowt*64, col0 = colt*64;
    __shared__ float As[16][68];
    __shared__ float Bs[16][68];
    int t = threadIdx.x;
    int tm4 = (t >> 4) * 4;
    int tn4 = (t & 15) * 4;
    ull acc2[8];
    #pragma unroll
    for (int q = 0; q < 8; q++) acc2[q] = 0ull;
    int kc = split*16;
    #pragma unroll
    for (int p = 0; p < 4; p++){
        int idx = t + p*256;
        int kk = idx & 15, m = idx >> 4;
        As[kk][m] = (row0 + m < rows) ? Aop[(size_t)(row0+m)*256 + kc + kk] : 0.f;
    }
    #pragma unroll
    for (int p = 0; p < 4; p++){
        int idx = t + p*256;
        int kk = idx & 15, j = idx >> 4;
        Bs[kk][j] = nt ? Bop[(size_t)(col0+j)*256 + kc + kk]
                       : Bop[(size_t)(kc+kk)*256 + col0 + j];
    }
    __syncthreads();
    #pragma unroll
    for (int kk = 0; kk < 16; kk++){
        float4 av = *(const float4*)&As[kk][tm4];
        ull bv0 = *(const ull*)&Bs[kk][tn4];
        ull bv1 = *(const ull*)&Bs[kk][tn4+2];
        ull a0 = dup2(av.x), a1 = dup2(av.y), a2 = dup2(av.z), a3 = dup2(av.w);
        fma2(acc2[0], a0, bv0); fma2(acc2[1], a0, bv1);
        fma2(acc2[2], a1, bv0); fma2(acc2[3], a1, bv1);
        fma2(acc2[4], a2, bv0); fma2(acc2[5], a2, bv1);
        fma2(acc2[6], a3, bv0); fma2(acc2[7], a3, bv1);
    }
    #pragma unroll
    for (int a = 0; a < 4; a++){
        int m = row0 + tm4 + a;
        if (m < rows){
            float2 v0 = *(float2*)&acc2[a*2];
            float2 v1 = *(float2*)&acc2[a*2+1];
            float* dst = &Cop[(size_t)m*256 + col0 + tn4];
            atomicAdd(dst+0, v0.x);
            atomicAdd(dst+1, v0.y);
            atomicAdd(dst+2, v1.x);
            atomicAdd(dst+3, v1.y);
        }
    }
}

// ---------------- 5. WE[s][i][(2k+c)*96+u] = mag_k * sum_o w[i,o,k]*E[o,u] ---
__global__ void wegemm_kernel(const float* __restrict__ wr, const float* __restrict__ wi){
    int i = blockIdx.x, s = blockIdx.y;
    int T = seg_T(s);
    __shared__ float As[2][16][68];   // [o'][2k+c]
    __shared__ float Bs[2][16][98];   // [o'][u]
    const float* wrp = wr + ((size_t)(s*256 + i)*256)*32;
    const float* wip = wi + ((size_t)(s*256 + i)*256)*32;
    const float* E = g_E[s];
    int t = threadIdx.x;
    int a = t >> 4, b = t & 15;
    ull acc2[12];
    #pragma unroll
    for (int q = 0; q < 12; q++) acc2[q] = 0ull;

    #pragma unroll
    for (int p = 0; p < 2; p++){
        int idx = t + p*256;
        int o = idx >> 5, k = idx & 31;
        As[0][o][2*k]   = wrp[o*32 + k];
        As[0][o][2*k+1] = wip[o*32 + k];
    }
    #pragma unroll
    for (int p = 0; p < 6; p++){
        int idx = t + p*256;
        int o = idx / 96, u = idx - o*96;
        Bs[0][o][u] = E[o*96 + u];
    }
    __syncthreads();

    float rr[2], ri[2], re[6];
    for (int c = 0; c < 16; c++){
        int cur = c & 1;
        if (c < 15){
            int oc = (c+1)*16;
            #pragma unroll
            for (int p = 0; p < 2; p++){
                int idx = t + p*256;
                int o = idx >> 5, k = idx & 31;
                rr[p] = wrp[(oc+o)*32 + k];
                ri[p] = wip[(oc+o)*32 + k];
            }
            #pragma unroll
            for (int p = 0; p < 6; p++){
                int idx = t + p*256;
                int o = idx / 96, u = idx - o*96;
                re[p] = E[(oc+o)*96 + u];
            }
        }
        #pragma unroll
        for (int o = 0; o < 16; o++){
            float4 av = *(const float4*)&As[cur][o][a*4];
            ull b0 = *(const ull*)&Bs[cur][o][b*6];
            ull b1 = *(const ull*)&Bs[cur][o][b*6+2];
            ull b2 = *(const ull*)&Bs[cur][o][b*6+4];
            ull a0 = dup2(av.x), a1 = dup2(av.y), a2 = dup2(av.z), a3 = dup2(av.w);
            fma2(acc2[0],  a0, b0); fma2(acc2[1],  a0, b1); fma2(acc2[2],  a0, b2);
            fma2(acc2[3],  a1, b0); fma2(acc2[4],  a1, b1); fma2(acc2[5],  a1, b2);
            fma2(acc2[6],  a2, b0); fma2(acc2[7],  a2, b1); fma2(acc2[8],  a2, b2);
            fma2(acc2[9],  a3, b0); fma2(acc2[10], a3, b1); fma2(acc2[11], a3, b2);
        }
        if (c < 15){
            int nxt = cur ^ 1;
            #pragma unroll
            for (int p = 0; p < 2; p++){
                int idx = t + p*256;
                int o = idx >> 5, k = idx & 31;
                As[nxt][o][2*k]   = rr[p];
                As[nxt][o][2*k+1] = ri[p];
            }
            #pragma unroll
            for (int p = 0; p < 6; p++){
                int idx = t + p*256;
                int o = idx / 96, u = idx - o*96;
                Bs[nxt][o][u] = re[p];
            }
        }
        __syncthreads();
    }
    float invT = 1.f/(float)T;
    float* out = g_WE[s] + (size_t)i*NDIM;
    #pragma unroll
    for (int q = 0; q < 4; q++){
        int kc = a*4 + q;
        int k = kc >> 1;
        float mag = (k == 0) ? invT : 2.f*invT;
        #pragma unroll
        for (int j = 0; j < 3; j++){
            float2 v = *(float2*)&acc2[q*3+j];
            out[kc*96 + b*6 + 2*j]     = v.x*mag;
            out[kc*96 + b*6 + 2*j + 1] = v.y*mag;
        }
    }
}

// ---------------- 6. C = K @ WE  (per-scale, double-buffered) ----------------
__global__ void cgemm_kernel(){
    int colt = blockIdx.x;          // 0..95
    int rowt = blockIdx.y;          // 0..10
    int s = c_tile_s[rowt], row0 = c_tile_r[rowt];
    int Ts = seg_T(s), seg = seg_off(s);
    int col0 = colt*64;
    const float* A = &g_K[s][0][0];
    const float* B = g_WE[s];
    __shared__ float As[2][16][68];
    __shared__ float Bs[2][16][68];
    int t = threadIdx.x;
    int tm4 = (t >> 4) * 4;
    int tn4 = (t & 15) * 4;
    ull acc2[8];
    #pragma unroll
    for (int q = 0; q < 8; q++) acc2[q] = 0ull;

    #pragma unroll
    for (int p = 0; p < 4; p++){
        int idx = t + p*256;
        int kk = idx & 15, m = idx >> 4;
        As[0][kk][m] = (row0 + m < Ts) ? A[(size_t)(row0+m)*256 + kk] : 0.f;
    }
    #pragma unroll
    for (int p = 0; p < 4; p++){
        int idx = t + p*256;
        int j = idx & 63, kk = idx >> 6;
        Bs[0][kk][j] = B[(size_t)kk*NDIM + col0 + j];
    }
    __syncthreads();

    float ra[4], rb[4];
    for (int c = 0; c < 16; c++){
        int cur = c & 1;
        if (c < 15){
            int kc = (c+1)*16;
            #pragma unroll
            for (int p = 0; p < 4; p++){
                int idx = t + p*256;
                int kk = idx & 15, m = idx >> 4;
                ra[p] = (row0 + m < Ts) ? A[(size_t)(row0+m)*256 + kc + kk] : 0.f;
            }
            #pragma unroll
            for (int p = 0; p < 4; p++){
                int idx = t + p*256;
                int j = idx & 63, kk = idx >> 6;
                rb[p] = B[(size_t)(kc+kk)*NDIM + col0 + j];
            }
        }
        #pragma unroll
        for (int kk = 0; kk < 16; kk++){
            float4 av = *(const float4*)&As[cur][kk][tm4];
            ull bv0 = *(const ull*)&Bs[cur][kk][tn4];
            ull bv1 = *(const ull*)&Bs[cur][kk][tn4+2];
            ull a0 = dup2(av.x), a1 = dup2(av.y), a2 = dup2(av.z), a3 = dup2(av.w);
            fma2(acc2[0], a0, bv0); fma2(acc2[1], a0, bv1);
            fma2(acc2[2], a1, bv0); fma2(acc2[3], a1, bv1);
            fma2(acc2[4], a2, bv0); fma2(acc2[5], a2, bv1);
            fma2(acc2[6], a3, bv0); fma2(acc2[7], a3, bv1);
        }
        if (c < 15){
            int nxt = cur ^ 1;
            #pragma unroll
            for (int p = 0; p < 4; p++){
                int idx = t + p*256;
                As[nxt][idx & 15][idx >> 4] = ra[p];
            }
            #pragma unroll
            for (int p = 0; p < 4; p++){
                int idx = t + p*256;
                Bs[nxt][idx >> 6][idx & 63] = rb[p];
            }
        }
        __syncthreads();
    }
    #pragma unroll
    for (int a = 0; a < 4; a++){
        int row = row0 + tm4 + a;
        if (row < Ts){
            float* outp = &g_C[(size_t)(seg+row)*NDIM + col0 + tn4];
            *(float2*)outp       = *(float2*)&acc2[a*2];
            *(float2*)(outp + 2) = *(float2*)&acc2[a*2+1];
        }
    }
}

// ---------------- 7. prefix-sum chain, smem-staged ----------------
__global__ void chain_kernel(){
    int k = blockIdx.x;             // 0..31
    int s = blockIdx.y;             // 0..2
    int T = seg_T(s), seg = seg_off(s);
    int u = threadIdx.x;            // 0..95
    __shared__ float buf[2][CH_D][192];
    __shared__ float2 tw[384];
    for (int m = u; m < T; m += 96){
        float sv, cv;
        sincosf(6.28318530717958647692f*(float)m/(float)T, &sv, &cv);
        tw[m] = make_float2(cv, sv);
    }
    const float* Cb = g_C + (size_t)seg*NDIM + (2*k)*96;
    #pragma unroll
    for (int q = 0; q < 12; q++){
        int j = u + q*96;
        int row = j/48, col = j%48;
        ((float4*)buf[0][row])[col] = ((const float4*)(Cb + (size_t)row*NDIM))[col];
    }
    __syncthreads();
    int nch = T / CH_D;
    int m0 = ((96 - T) % T + T) % T;
    int p1 = 0;
    int p2 = (int)(((long long)k * (long long)m0) % (long long)T);
    float Pr = 0.f, Pi = 0.f;
    float* Mp = g_Mpart[s*32+k] + u;
    for (int c = 0; c < nch; c++){
        int cur = c & 1;
        if (c + 1 < nch){
            const float* src = Cb + (size_t)(c+1)*CH_D*NDIM;
            #pragma unroll
            for (int q = 0; q < 12; q++){
                int j = u + q*96;
                int row = j/48, col = j%48;
                ((float4*)buf[cur^1][row])[col] = ((const float4*)(src + (size_t)row*NDIM))[col];
            }
        }
        #pragma unroll 4
        for (int dd = 0; dd < CH_D; dd++){
            int d = c*CH_D + dd;
            float Cr = buf[cur][dd][u];
            float Ci = buf[cur][dd][u+96];
            float2 t1 = tw[p1];
            Pr += Cr*t1.x + Ci*t1.y;
            Pi += Ci*t1.x - Cr*t1.y;
            float2 t2 = tw[p2];
            Mp[(size_t)(383-d)*96] = t2.x*Pr - t2.y*Pi;
            p1 += k; if (p1 >= T) p1 -= T;
            p2 += k; if (p2 >= T) p2 -= T;
        }
        __syncthreads();
    }
}

// ---------------- 8. reduce Mpart over (s,k) with validity ranges ----------
__global__ void mreduce_kernel(){
    int idx = blockIdx.x*256 + threadIdx.x;   // 0..36863
    if (idx >= 384*96) return;
    int g = idx / 96;
    float a = 0.f;
    #pragma unroll 8
    for (int p = 64; p < 96; p++) a += g_Mpart[p][idx];   // s2: all g
    if (g >= 192){
        #pragma unroll 8
        for (int p = 32; p < 64; p++) a += g_Mpart[p][idx];
    }
    if (g >= 288){
        #pragma unroll 8
        for (int p = 0; p < 32; p++) a += g_Mpart[p][idx];
    }
    g_M[idx] = a;
}

// ---------------- 9. final (msum folded in) ----------------
__global__ void final_kernel(const float* __restrict__ x,
                             const float* __restrict__ mlp_b,
                             float* __restrict__ out){
    int b = blockIdx.x, u = blockIdx.y;
    int e = threadIdx.x;   // 64
    __shared__ float msh[384];
    for (int g = e; g < 384; g += 64) msh[g] = g_M[g*96 + u];
    __syncthreads();
    const float* xp = x + ((size_t)b*LSEQ + 336)*ECH + e;
    float acc = 0.f, msum = 0.f;
    #pragma unroll 8
    for (int g = 0; g < 384; g++){
        float mv = msh[g];
        acc += xp[(size_t)g*ECH] * mv;
        msum += mv;
    }
    float mean = g_mean[b*ECH+e], sd = g_std[b*ECH+e];
    out[((size_t)b*OUTL + u)*ECH + e] = acc + mean*(1.f - msum) + mlp_b[0]*sd;
}

// ---------------- launch (multi-stream fork/join, graph-capturable) --------
extern "C" void kernel_launch(void* const* d_in, const int* in_sizes, int n_in,
                              void* d_out, int out_size){
    const float* x     = (const float*)d_in[0];
    const float* wr    = (const float*)d_in[1];
    const float* wi    = (const float*)d_in[2];
    const float* mlp_w = (const float*)d_in[3];
    const float* mlp_b = (const float*)d_in[4];
    const float* A     = (const float*)d_in[5];
    const float* Bv    = (const float*)d_in[6];
    const float* ev    = (const float*)d_in[7];
    float* out = (float*)d_out;

    static cudaStream_t sB = 0;
    static cudaEvent_t eFork = 0, eB = 0;
    if (!sB){
        cudaStreamCreateWithFlags(&sB, cudaStreamNonBlocking);
        cudaEventCreateWithFlags(&eFork, cudaEventDisableTiming);
        cudaEventCreateWithFlags(&eB, cudaEventDisableTiming);
    }

    // fork
    cudaEventRecord(eFork, 0);
    cudaStreamWaitEvent(sB, eFork, 0);

    // stream B: stats+egen merged, then weight-side GEMM
    prep_kernel<<<BATCH+3, 256, 0, sB>>>(x, ev, mlp_w);
    wegemm_kernel<<<dim3(256,3), 256, 0, sB>>>(wr, wi);
    cudaEventRecord(eB, sB);

    // stream 0: Krylov rounds (split-K=16, single pass per block)
    init_kernel<<<(N1+N2+N3+255)/256, 256>>>(A, Bv);
    for (int r = 0; r < 9; r++)
        rgemm_kernel<<<dim3(16,3,32), 256>>>(r);

    // join B, then the tail
    cudaStreamWaitEvent(0, eB, 0);
    cgemm_kernel<<<dim3(96,11), 256>>>();
    chain_kernel<<<dim3(32,3), 96>>>();
    mreduce_kernel<<<144, 256>>>();
    final_kernel<<<dim3(BATCH, OUTL), 64>>>(x, mlp_b, out);
}

// round 14
// speedup vs baseline: 1.2132x; 1.0768x over previous
#include <cuda_runtime.h>
#include <math.h>

#define BATCH 16
#define LSEQ  720
#define ECH   64
#define OUTL  96
#define NDIM  6144            // (2k+c)*96+u = 64*96
#define CH_D  24

typedef unsigned long long ull;

__device__ __forceinline__ ull dup2(float x){
    ull r;
    asm("mov.b64 %0, {%1, %1};" : "=l"(r) : "f"(x));
    return r;
}
__device__ __forceinline__ void fma2(ull &d, ull a, ull b){
    asm("fma.rn.f32x2 %0, %1, %2, %0;" : "+l"(d) : "l"(a), "l"(b));
}
__device__ __forceinline__ void red4(float* p, float x, float y, float z, float w){
    asm volatile("red.global.add.v4.f32 [%0], {%1,%2,%3,%4};"
                 :: "l"(p), "f"(x), "f"(y), "f"(z), "f"(w) : "memory");
}

// ---------------- static device scratch ----------------
__device__ float g_mean[BATCH*ECH];
__device__ float g_std [BATCH*ECH];
__device__ float g_K[3][384][256];            // Krylov kernels K_d = Ad^d Bd (red dst)
__device__ float g_Pw[10][3][65536];          // P^(2^r) per round (red dst for r>=1)
__device__ float g_E[3][256*96];              // mlp_w[s]*ev[s]^T  (o,u)
__device__ float g_WE[3][256*NDIM];           // Wc@E, mag folded
__device__ float g_C[672*NDIM];               // K@WE
__device__ float g_Mpart[96][384*96];         // per (s,k) chain partials
__device__ float g_M[384*96];

__constant__ int c_tile_s[11] = {0,0,1,1,1,2,2,2,2,2,2};
__constant__ int c_tile_r[11] = {0,64,0,64,128,0,64,128,192,256,320};

__device__ __forceinline__ int seg_off(int s){ return s==0?0:(s==1?96:288); }
__device__ __forceinline__ int seg_T  (int s){ return s==0?96:(s==1?192:384); }

// ---------------- 1. merged prep: blocks 0..15 stats, 16..18 egen ----------
__global__ void prep_kernel(const float* __restrict__ x,
                            const float* __restrict__ ev,
                            const float* __restrict__ mlp_w){
    int bid = blockIdx.x;
    int t = threadIdx.x;
    if (bid < BATCH){
        int b = bid;
        int e = t & 63, q = t >> 6;
        float s = 0.f, sq = 0.f;
        for (int l = q; l < LSEQ; l += 4){
            float v = x[((size_t)b*LSEQ + l)*ECH + e];
            s += v; sq += v*v;
        }
        __shared__ float sh[2][4][64];
        sh[0][q][e] = s; sh[1][q][e] = sq;
        __syncthreads();
        if (q == 0){
            float S  = sh[0][0][e]+sh[0][1][e]+sh[0][2][e]+sh[0][3][e];
            float SQ = sh[1][0][e]+sh[1][1][e]+sh[1][2][e]+sh[1][3][e];
            float m = S * (1.f/LSEQ);
            float var = SQ * (1.f/LSEQ) - m*m;
            g_mean[b*ECH+e] = m;
            g_std [b*ECH+e] = sqrtf(var + 1e-5f);
        }
    } else {
        int s = bid - BATCH;
        int o = t;
        float w = mlp_w[s];
        for (int u = 0; u < 96; u++)
            g_E[s][o*96 + u] = w * ev[((size_t)(s*96+u))*256 + o];
    }
}

// ---------------- 3. init: Pw[0]=Ad; zero Pw[1..9]; K row0=Bd, rest 0 -------
#define N1 196608          // 3*65536
#define N2 1769472         // 9*3*65536
#define N3 294912          // 3*384*256
__global__ void init_kernel(const float* __restrict__ A, const float* __restrict__ Bv){
    int idx = blockIdx.x*blockDim.x + threadIdx.x;
    float* pw = &g_Pw[0][0][0];
    if (idx < N1){
        pw[idx] = A[idx];
    } else if (idx < N1 + N2){
        pw[idx] = 0.f;
    } else if (idx < N1 + N2 + N3){
        int j = idx - (N1 + N2);
        int s = j / 98304, rem = j % 98304;
        int d = rem >> 8, i = rem & 255;
        g_K[s][d][i] = d ? 0.f : Bv[s*256 + i];
    }
}

// ---------------- 4. log-doubling round (split-K=8, vector red) -------------
// task 0: K[n..n+m) += K[0..m) @ (P^n)^T   (m=min(n,T-n))
// task 1: P^{2n}    += P^n @ P^n           (only if 2n < T)
__global__ void rgemm_kernel(int r){
    int s = blockIdx.y;
    int task  = blockIdx.z >> 3;
    int split = blockIdx.z & 7;
    int Ts = seg_T(s);
    int n = 1 << r;
    int rows; const float *Aop, *Bop; float* Cop; bool nt;
    if (task == 0){
        if (n >= Ts) return;
        rows = min(n, Ts - n);
        Aop = &g_K[s][0][0];
        Bop = g_Pw[r][s];
        Cop = &g_K[s][n][0];
        nt  = true;
    } else {
        if (2*n >= Ts) return;
        rows = 256;
        Aop = g_Pw[r][s];
        Bop = Aop;
        Cop = g_Pw[r+1][s];
        nt  = false;
    }
    int tile = blockIdx.x;
    int rowt = tile >> 2, colt = tile & 3;
    if (rowt*64 >= rows) return;
    int row0 = rowt*64, col0 = colt*64;
    __shared__ float As[16][68];
    __shared__ float Bs[16][68];
    int t = threadIdx.x;
    int tm4 = (t >> 4) * 4;
    int tn4 = (t & 15) * 4;
    ull acc2[8];
    #pragma unroll
    for (int q = 0; q < 8; q++) acc2[q] = 0ull;
    int k0 = split*32;
    #pragma unroll
    for (int ch = 0; ch < 2; ch++){
        int kc = k0 + ch*16;
        #pragma unroll
        for (int p = 0; p < 4; p++){
            int idx = t + p*256;
            int kk = idx & 15, m = idx >> 4;
            As[kk][m] = (row0 + m < rows) ? Aop[(size_t)(row0+m)*256 + kc + kk] : 0.f;
        }
        #pragma unroll
        for (int p = 0; p < 4; p++){
            int idx = t + p*256;
            int kk = idx & 15, j = idx >> 4;
            Bs[kk][j] = nt ? Bop[(size_t)(col0+j)*256 + kc + kk]
                           : Bop[(size_t)(kc+kk)*256 + col0 + j];
        }
        __syncthreads();
        #pragma unroll
        for (int kk = 0; kk < 16; kk++){
            float4 av = *(const float4*)&As[kk][tm4];
            ull bv0 = *(const ull*)&Bs[kk][tn4];
            ull bv1 = *(const ull*)&Bs[kk][tn4+2];
            ull a0 = dup2(av.x), a1 = dup2(av.y), a2 = dup2(av.z), a3 = dup2(av.w);
            fma2(acc2[0], a0, bv0); fma2(acc2[1], a0, bv1);
            fma2(acc2[2], a1, bv0); fma2(acc2[3], a1, bv1);
            fma2(acc2[4], a2, bv0); fma2(acc2[5], a2, bv1);
            fma2(acc2[6], a3, bv0); fma2(acc2[7], a3, bv1);
        }
        __syncthreads();
    }
    #pragma unroll
    for (int a = 0; a < 4; a++){
        int m = row0 + tm4 + a;
        if (m < rows){
            float2 v0 = *(float2*)&acc2[a*2];
            float2 v1 = *(float2*)&acc2[a*2+1];
            red4(&Cop[(size_t)m*256 + col0 + tn4], v0.x, v0.y, v1.x, v1.y);
        }
    }
}

// ---------------- 5. WE[s][i][(2k+c)*96+u] = mag_k * sum_o w[i,o,k]*E[o,u] ---
__global__ void wegemm_kernel(const float* __restrict__ wr, const float* __restrict__ wi){
    int i = blockIdx.x, s = blockIdx.y;
    int T = seg_T(s);
    __shared__ float As[2][16][68];   // [o'][2k+c]
    __shared__ float Bs[2][16][98];   // [o'][u]
    const float* wrp = wr + ((size_t)(s*256 + i)*256)*32;
    const float* wip = wi + ((size_t)(s*256 + i)*256)*32;
    const float* E = g_E[s];
    int t = threadIdx.x;
    int a = t >> 4, b = t & 15;
    ull acc2[12];
    #pragma unroll
    for (int q = 0; q < 12; q++) acc2[q] = 0ull;

    #pragma unroll
    for (int p = 0; p < 2; p++){
        int idx = t + p*256;
        int o = idx >> 5, k = idx & 31;
        As[0][o][2*k]   = wrp[o*32 + k];
        As[0][o][2*k+1] = wip[o*32 + k];
    }
    #pragma unroll
    for (int p = 0; p < 6; p++){
        int idx = t + p*256;
        int o = idx / 96, u = idx - o*96;
        Bs[0][o][u] = E[o*96 + u];
    }
    __syncthreads();

    float rr[2], ri[2], re[6];
    for (int c = 0; c < 16; c++){
        int cur = c & 1;
        if (c < 15){
            int oc = (c+1)*16;
            #pragma unroll
            for (int p = 0; p < 2; p++){
                int idx = t + p*256;
                int o = idx >> 5, k = idx & 31;
                rr[p] = wrp[(oc+o)*32 + k];
                ri[p] = wip[(oc+o)*32 + k];
            }
            #pragma unroll
            for (int p = 0; p < 6; p++){
                int idx = t + p*256;
                int o = idx / 96, u = idx - o*96;
                re[p] = E[(oc+o)*96 + u];
            }
        }
        #pragma unroll
        for (int o = 0; o < 16; o++){
            float4 av = *(const float4*)&As[cur][o][a*4];
            ull b0 = *(const ull*)&Bs[cur][o][b*6];
            ull b1 = *(const ull*)&Bs[cur][o][b*6+2];
            ull b2 = *(const ull*)&Bs[cur][o][b*6+4];
            ull a0 = dup2(av.x), a1 = dup2(av.y), a2 = dup2(av.z), a3 = dup2(av.w);
            fma2(acc2[0],  a0, b0); fma2(acc2[1],  a0, b1); fma2(acc2[2],  a0, b2);
            fma2(acc2[3],  a1, b0); fma2(acc2[4],  a1, b1); fma2(acc2[5],  a1, b2);
            fma2(acc2[6],  a2, b0); fma2(acc2[7],  a2, b1); fma2(acc2[8],  a2, b2);
            fma2(acc2[9],  a3, b0); fma2(acc2[10], a3, b1); fma2(acc2[11], a3, b2);
        }
        if (c < 15){
            int nxt = cur ^ 1;
            #pragma unroll
            for (int p = 0; p < 2; p++){
                int idx = t + p*256;
                int o = idx >> 5, k = idx & 31;
                As[nxt][o][2*k]   = rr[p];
                As[nxt][o][2*k+1] = ri[p];
            }
            #pragma unroll
            for (int p = 0; p < 6; p++){
                int idx = t + p*256;
                int o = idx / 96, u = idx - o*96;
                Bs[nxt][o][u] = re[p];
            }
        }
        __syncthreads();
    }
    float invT = 1.f/(float)T;
    float* out = g_WE[s] + (size_t)i*NDIM;
    #pragma unroll
    for (int q = 0; q < 4; q++){
        int kc = a*4 + q;
        int k = kc >> 1;
        float mag = (k == 0) ? invT : 2.f*invT;
        #pragma unroll
        for (int j = 0; j < 3; j++){
            float2 v = *(float2*)&acc2[q*3+j];
            out[kc*96 + b*6 + 2*j]     = v.x*mag;
            out[kc*96 + b*6 + 2*j + 1] = v.y*mag;
        }
    }
}

// ---------------- 6. C = K @ WE  (per-scale, double-buffered) ----------------
__global__ void cgemm_kernel(){
    int colt = blockIdx.x;          // 0..95
    int rowt = blockIdx.y;          // 0..10
    int s = c_tile_s[rowt], row0 = c_tile_r[rowt];
    int Ts = seg_T(s), seg = seg_off(s);
    int col0 = colt*64;
    const float* A = &g_K[s][0][0];
    const float* B = g_WE[s];
    __shared__ float As[2][16][68];
    __shared__ float Bs[2][16][68];
    int t = threadIdx.x;
    int tm4 = (t >> 4) * 4;
    int tn4 = (t & 15) * 4;
    ull acc2[8];
    #pragma unroll
    for (int q = 0; q < 8; q++) acc2[q] = 0ull;

    #pragma unroll
    for (int p = 0; p < 4; p++){
        int idx = t + p*256;
        int kk = idx & 15, m = idx >> 4;
        As[0][kk][m] = (row0 + m < Ts) ? A[(size_t)(row0+m)*256 + kk] : 0.f;
    }
    #pragma unroll
    for (int p = 0; p < 4; p++){
        int idx = t + p*256;
        int j = idx & 63, kk = idx >> 6;
        Bs[0][kk][j] = B[(size_t)kk*NDIM + col0 + j];
    }
    __syncthreads();

    float ra[4], rb[4];
    for (int c = 0; c < 16; c++){
        int cur = c & 1;
        if (c < 15){
            int kc = (c+1)*16;
            #pragma unroll
            for (int p = 0; p < 4; p++){
                int idx = t + p*256;
                int kk = idx & 15, m = idx >> 4;
                ra[p] = (row0 + m < Ts) ? A[(size_t)(row0+m)*256 + kc + kk] : 0.f;
            }
            #pragma unroll
            for (int p = 0; p < 4; p++){
                int idx = t + p*256;
                int j = idx & 63, kk = idx >> 6;
                rb[p] = B[(size_t)(kc+kk)*NDIM + col0 + j];
            }
        }
        #pragma unroll
        for (int kk = 0; kk < 16; kk++){
            float4 av = *(const float4*)&As[cur][kk][tm4];
            ull bv0 = *(const ull*)&Bs[cur][kk][tn4];
            ull bv1 = *(const ull*)&Bs[cur][kk][tn4+2];
            ull a0 = dup2(av.x), a1 = dup2(av.y), a2 = dup2(av.z), a3 = dup2(av.w);
            fma2(acc2[0], a0, bv0); fma2(acc2[1], a0, bv1);
            fma2(acc2[2], a1, bv0); fma2(acc2[3], a1, bv1);
            fma2(acc2[4], a2, bv0); fma2(acc2[5], a2, bv1);
            fma2(acc2[6], a3, bv0); fma2(acc2[7], a3, bv1);
        }
        if (c < 15){
            int nxt = cur ^ 1;
            #pragma unroll
            for (int p = 0; p < 4; p++){
                int idx = t + p*256;
                As[nxt][idx & 15][idx >> 4] = ra[p];
            }
            #pragma unroll
            for (int p = 0; p < 4; p++){
                int idx = t + p*256;
                Bs[nxt][idx >> 6][idx & 63] = rb[p];
            }
        }
        __syncthreads();
    }
    #pragma unroll
    for (int a = 0; a < 4; a++){
        int row = row0 + tm4 + a;
        if (row < Ts){
            float* outp = &g_C[(size_t)(seg+row)*NDIM + col0 + tn4];
            *(float2*)outp       = *(float2*)&acc2[a*2];
            *(float2*)(outp + 2) = *(float2*)&acc2[a*2+1];
        }
    }
}

// ---------------- 7. prefix-sum chain, smem-staged ----------------
__global__ void chain_kernel(){
    int k = blockIdx.x;             // 0..31
    int s = blockIdx.y;             // 0..2
    int T = seg_T(s), seg = seg_off(s);
    int u = threadIdx.x;            // 0..95
    __shared__ float buf[2][CH_D][192];
    __shared__ float2 tw[384];
    for (int m = u; m < T; m += 96){
        float sv, cv;
        sincosf(6.28318530717958647692f*(float)m/(float)T, &sv, &cv);
        tw[m] = make_float2(cv, sv);
    }
    const float* Cb = g_C + (size_t)seg*NDIM + (2*k)*96;
    #pragma unroll
    for (int q = 0; q < 12; q++){
        int j = u + q*96;
        int row = j/48, col = j%48;
        ((float4*)buf[0][row])[col] = ((const float4*)(Cb + (size_t)row*NDIM))[col];
    }
    __syncthreads();
    int nch = T / CH_D;
    int m0 = ((96 - T) % T + T) % T;
    int p1 = 0;
    int p2 = (int)(((long long)k * (long long)m0) % (long long)T);
    float Pr = 0.f, Pi = 0.f;
    float* Mp = g_Mpart[s*32+k] + u;
    for (int c = 0; c < nch; c++){
        int cur = c & 1;
        if (c + 1 < nch){
            const float* src = Cb + (size_t)(c+1)*CH_D*NDIM;
            #pragma unroll
            for (int q = 0; q < 12; q++){
                int j = u + q*96;
                int row = j/48, col = j%48;
                ((float4*)buf[cur^1][row])[col] = ((const float4*)(src + (size_t)row*NDIM))[col];
            }
        }
        #pragma unroll 4
        for (int dd = 0; dd < CH_D; dd++){
            int d = c*CH_D + dd;
            float Cr = buf[cur][dd][u];
            float Ci = buf[cur][dd][u+96];
            float2 t1 = tw[p1];
            Pr += Cr*t1.x + Ci*t1.y;
            Pi += Ci*t1.x - Cr*t1.y;
            float2 t2 = tw[p2];
            Mp[(size_t)(383-d)*96] = t2.x*Pr - t2.y*Pi;
            p1 += k; if (p1 >= T) p1 -= T;
            p2 += k; if (p2 >= T) p2 -= T;
        }
        __syncthreads();
    }
}

// ---------------- 8. reduce Mpart over (s,k) with validity ranges ----------
__global__ void mreduce_kernel(){
    int idx = blockIdx.x*256 + threadIdx.x;   // 0..36863
    if (idx >= 384*96) return;
    int g = idx / 96;
    float a = 0.f;
    #pragma unroll 8
    for (int p = 64; p < 96; p++) a += g_Mpart[p][idx];   // s2: all g
    if (g >= 192){
        #pragma unroll 8
        for (int p = 32; p < 64; p++) a += g_Mpart[p][idx];
    }
    if (g >= 288){
        #pragma unroll 8
        for (int p = 0; p < 32; p++) a += g_Mpart[p][idx];
    }
    g_M[idx] = a;
}

// ---------------- 9. final (msum folded in) ----------------
__global__ void final_kernel(const float* __restrict__ x,
                             const float* __restrict__ mlp_b,
                             float* __restrict__ out){
    int b = blockIdx.x, u = blockIdx.y;
    int e = threadIdx.x;   // 64
    __shared__ float msh[384];
    for (int g = e; g < 384; g += 64) msh[g] = g_M[g*96 + u];
    __syncthreads();
    const float* xp = x + ((size_t)b*LSEQ + 336)*ECH + e;
    float acc = 0.f, msum = 0.f;
    #pragma unroll 8
    for (int g = 0; g < 384; g++){
        float mv = msh[g];
        acc += xp[(size_t)g*ECH] * mv;
        msum += mv;
    }
    float mean = g_mean[b*ECH+e], sd = g_std[b*ECH+e];
    out[((size_t)b*OUTL + u)*ECH + e] = acc + mean*(1.f - msum) + mlp_b[0]*sd;
}

// ---------------- launch (multi-stream fork/join, graph-capturable) --------
extern "C" void kernel_launch(void* const* d_in, const int* in_sizes, int n_in,
                              void* d_out, int out_size){
    const float* x     = (const float*)d_in[0];
    const float* wr    = (const float*)d_in[1];
    const float* wi    = (const float*)d_in[2];
    const float* mlp_w = (const float*)d_in[3];
    const float* mlp_b = (const float*)d_in[4];
    const float* A     = (const float*)d_in[5];
    const float* Bv    = (const float*)d_in[6];
    const float* ev    = (const float*)d_in[7];
    float* out = (float*)d_out;

    static cudaStream_t sB = 0;
    static cudaEvent_t eFork = 0, eB = 0;
    if (!sB){
        cudaStreamCreateWithFlags(&sB, cudaStreamNonBlocking);
        cudaEventCreateWithFlags(&eFork, cudaEventDisableTiming);
        cudaEventCreateWithFlags(&eB, cudaEventDisableTiming);
    }

    // fork
    cudaEventRecord(eFork, 0);
    cudaStreamWaitEvent(sB, eFork, 0);

    // stream B: stats+egen merged, then weight-side GEMM
    prep_kernel<<<BATCH+3, 256, 0, sB>>>(x, ev, mlp_w);
    wegemm_kernel<<<dim3(256,3), 256, 0, sB>>>(wr, wi);
    cudaEventRecord(eB, sB);

    // stream 0: Krylov rounds (split-K=8, vector red)
    init_kernel<<<(N1+N2+N3+255)/256, 256>>>(A, Bv);
    for (int r = 0; r < 9; r++)
        rgemm_kernel<<<dim3(16,3,16), 256>>>(r);

    // join B, then the tail
    cudaStreamWaitEvent(0, eB, 0);
    cgemm_kernel<<<dim3(96,11), 256>>>();
    chain_kernel<<<dim3(32,3), 96>>>();
    mreduce_kernel<<<144, 256>>>();
    final_kernel<<<dim3(BATCH, OUTL), 64>>>(x, mlp_b, out);
}